// round 4
// baseline (speedup 1.0000x reference)
#include <cuda_runtime.h>

#define NN 50000
#define EE 800000
#define KDIM 128
#define DHID 128
#define DOUT 64

// ---------------- scratch (device globals; no allocs allowed) ----------------
__device__ int g_is64;             // 1 if edge_index is int64, 0 if int32
__device__ int g_deg[NN];
__device__ int g_rowstart[NN + 1];
__device__ int g_cursor[NN];
__device__ int g_esrc[EE];

__device__ float g_zl[NN * DHID];  // x @ W_l1  (gets aggregated)
__device__ float g_zr[NN * DHID];  // x @ W_r1  (self term)
__device__ float g_h [NN * DHID];  // layer-1 output
__device__ float g_ul[NN * DOUT];  // h @ W_l2  (gets aggregated)
__device__ float g_ur[NN * DOUT];  // h @ W_r2  (self term)

// ---------------- edge dtype detection ----------------
// int64 little-endian with values in [0, NN): odd 32-bit words are all 0.
// int32: odd words are random edge endpoints, ~never all zero over 1024 samples.
__global__ void detect_kernel(const int* __restrict__ ei32) {
    __shared__ int nz;
    if (threadIdx.x == 0) nz = 0;
    __syncthreads();
    for (int i = threadIdx.x; i < 1024; i += blockDim.x) {
        if (ei32[2 * i + 1] != 0) nz = 1;   // benign race
    }
    __syncthreads();
    if (threadIdx.x == 0) g_is64 = (nz == 0) ? 1 : 0;
}

__device__ __forceinline__ int load_src(const void* ei, int e) {
    return g_is64 ? (int)((const long long*)ei)[e] : ((const int*)ei)[e];
}
__device__ __forceinline__ int load_dst(const void* ei, int e) {
    return g_is64 ? (int)((const long long*)ei)[EE + e] : ((const int*)ei)[EE + e];
}

// ---------------- CSR build ----------------
__global__ void zero_deg_kernel() {
    int i = blockIdx.x * blockDim.x + threadIdx.x;
    if (i < NN) g_deg[i] = 0;
}

__global__ void hist_kernel(const void* __restrict__ ei) {
    int e = blockIdx.x * blockDim.x + threadIdx.x;
    if (e < EE) {
        int d = load_dst(ei, e);
        if ((unsigned)d < NN) atomicAdd(&g_deg[d], 1);
    }
}

// single-block exclusive scan over deg -> rowstart, cursor
__global__ void scan_kernel() {
    __shared__ int sums[1024];
    const int t = threadIdx.x;
    const int CH = (NN + 1023) / 1024;  // 49
    int lo = t * CH;
    int hi = lo + CH;
    if (lo > NN) lo = NN;
    if (hi > NN) hi = NN;
    int s = 0;
    for (int i = lo; i < hi; i++) s += g_deg[i];
    sums[t] = s;
    __syncthreads();
    // inclusive Hillis-Steele
    for (int off = 1; off < 1024; off <<= 1) {
        int v = (t >= off) ? sums[t - off] : 0;
        __syncthreads();
        sums[t] += v;
        __syncthreads();
    }
    int base = (t == 0) ? 0 : sums[t - 1];
    for (int i = lo; i < hi; i++) {
        int d = g_deg[i];
        g_rowstart[i] = base;
        g_cursor[i]   = base;
        base += d;
    }
    if (t == 1023) g_rowstart[NN] = sums[1023];
}

__global__ void fill_kernel(const void* __restrict__ ei) {
    int e = blockIdx.x * blockDim.x + threadIdx.x;
    if (e < EE) {
        int d = load_dst(ei, e);
        int s = load_src(ei, e);
        if ((unsigned)d < NN && (unsigned)s < NN) {
            int pos = atomicAdd(&g_cursor[d], 1);
            g_esrc[pos] = s;
        }
    }
}

// ---------------- fp32 tiled GEMM body: C[M x BN] = A[M x 128] @ B[128 x BN] ----------------
// BM=128, BK=16, 256 threads, TMxTN register tiles. Scratch buffers are bound
// in DEVICE code by thin wrappers (device-formed addresses are always valid).
template <int BN, int TN>
__device__ __forceinline__
void gemm_body(const float* __restrict__ A, const float* __restrict__ B,
               float* __restrict__ C) {
    const int BM = 128, BK = 16, K = KDIM, TM = 8, M = NN;
    __shared__ float As[BK][BM + 4];
    __shared__ float Bs[BK][BN];

    const int tid = threadIdx.x;
    const int tx = tid % (BN / TN);    // column-threads
    const int ty = tid / (BN / TN);    // row-threads
    const int row0 = blockIdx.x * BM;

    float acc[TM][TN];
#pragma unroll
    for (int i = 0; i < TM; i++)
#pragma unroll
        for (int n = 0; n < TN; n++) acc[i][n] = 0.0f;

    for (int k0 = 0; k0 < K; k0 += BK) {
        // load A tile (BM x BK), store transposed into As[k][m]
#pragma unroll
        for (int p = 0; p < (BM * BK) / (256 * 4); p++) {
            int idx = (p * 256 + tid) * 4;
            int m = idx / BK;
            int kk = idx % BK;       // multiple of 4
            float4 v = make_float4(0.f, 0.f, 0.f, 0.f);
            int row = row0 + m;
            if (row < M) v = *(const float4*)&A[row * K + k0 + kk];
            As[kk + 0][m] = v.x;
            As[kk + 1][m] = v.y;
            As[kk + 2][m] = v.z;
            As[kk + 3][m] = v.w;
        }
        // load B tile (BK x BN)
#pragma unroll
        for (int p = 0; p < (BK * BN) / (256 * 4); p++) {
            int idx = (p * 256 + tid) * 4;
            int kk = idx / BN;
            int j = idx % BN;
            *(float4*)&Bs[kk][j] = *(const float4*)&B[(k0 + kk) * BN + j];
        }
        __syncthreads();

#pragma unroll
        for (int k = 0; k < BK; k++) {
            float a[TM];
            *(float4*)&a[0] = *(const float4*)&As[k][ty * TM];
            *(float4*)&a[4] = *(const float4*)&As[k][ty * TM + 4];
            float b[TN];
            *(float4*)&b[0] = *(const float4*)&Bs[k][tx * TN];
            if constexpr (TN == 8) {
                *(float4*)&b[4] = *(const float4*)&Bs[k][tx * TN + 4];
            }
#pragma unroll
            for (int i = 0; i < TM; i++)
#pragma unroll
                for (int n = 0; n < TN; n++) acc[i][n] = fmaf(a[i], b[n], acc[i][n]);
        }
        __syncthreads();
    }

#pragma unroll
    for (int i = 0; i < TM; i++) {
        int row = row0 + ty * TM + i;
        if (row < M) {
#pragma unroll
            for (int n = 0; n < TN; n += 4) {
                float4 v = make_float4(acc[i][n], acc[i][n + 1], acc[i][n + 2], acc[i][n + 3]);
                *(float4*)&C[row * BN + tx * TN + n] = v;
            }
        }
    }
}

// Wrappers: scratch buffers bound on the DEVICE side only.
__global__ __launch_bounds__(256) void gemm_zl_kernel(const float* __restrict__ x,
                                                      const float* __restrict__ W) {
    gemm_body<128, 8>(x, W, g_zl);
}
__global__ __launch_bounds__(256) void gemm_zr_kernel(const float* __restrict__ x,
                                                      const float* __restrict__ W) {
    gemm_body<128, 8>(x, W, g_zr);
}
__global__ __launch_bounds__(256) void gemm_ul_kernel(const float* __restrict__ W) {
    gemm_body<64, 4>(g_h, W, g_ul);
}
__global__ __launch_bounds__(256) void gemm_ur_kernel(const float* __restrict__ W) {
    gemm_body<64, 4>(g_h, W, g_ur);
}

// ---------------- fused mean-aggregate + epilogue ----------------
// layer 1: h = relu(mean_agg(zl) + zr + b1), D=128, one warp per node, float4/lane
__global__ void agg_epi1_kernel(const float* __restrict__ b1) {
    int gw = (blockIdx.x * blockDim.x + threadIdx.x) >> 5;
    if (gw >= NN) return;
    int lane = threadIdx.x & 31;
    int c = lane * 4;
    int lo = g_rowstart[gw], hi = g_rowstart[gw + 1];

    float4 acc = make_float4(0.f, 0.f, 0.f, 0.f);
    int j = lo;
    for (; j + 4 <= hi; j += 4) {
        int s0 = g_esrc[j], s1 = g_esrc[j + 1], s2 = g_esrc[j + 2], s3 = g_esrc[j + 3];
        float4 v0 = *(const float4*)&g_zl[s0 * DHID + c];
        float4 v1 = *(const float4*)&g_zl[s1 * DHID + c];
        float4 v2 = *(const float4*)&g_zl[s2 * DHID + c];
        float4 v3 = *(const float4*)&g_zl[s3 * DHID + c];
        acc.x += (v0.x + v1.x) + (v2.x + v3.x);
        acc.y += (v0.y + v1.y) + (v2.y + v3.y);
        acc.z += (v0.z + v1.z) + (v2.z + v3.z);
        acc.w += (v0.w + v1.w) + (v2.w + v3.w);
    }
    for (; j < hi; j++) {
        int s = g_esrc[j];
        float4 v = *(const float4*)&g_zl[s * DHID + c];
        acc.x += v.x; acc.y += v.y; acc.z += v.z; acc.w += v.w;
    }
    float invd = 1.0f / (float)max(hi - lo, 1);
    float4 r  = *(const float4*)&g_zr[gw * DHID + c];
    float4 bb = *(const float4*)&b1[c];
    float4 o;
    o.x = fmaxf(fmaf(acc.x, invd, r.x + bb.x), 0.f);
    o.y = fmaxf(fmaf(acc.y, invd, r.y + bb.y), 0.f);
    o.z = fmaxf(fmaf(acc.z, invd, r.z + bb.z), 0.f);
    o.w = fmaxf(fmaf(acc.w, invd, r.w + bb.w), 0.f);
    *(float4*)&g_h[gw * DHID + c] = o;
}

// layer 2: out = mean_agg(ul) + ur + b2, D=64, one warp per node, float2/lane
__global__ void agg_epi2_kernel(const float* __restrict__ b2, float* __restrict__ out) {
    int gw = (blockIdx.x * blockDim.x + threadIdx.x) >> 5;
    if (gw >= NN) return;
    int lane = threadIdx.x & 31;
    int c = lane * 2;
    int lo = g_rowstart[gw], hi = g_rowstart[gw + 1];

    float2 acc = make_float2(0.f, 0.f);
    int j = lo;
    for (; j + 4 <= hi; j += 4) {
        int s0 = g_esrc[j], s1 = g_esrc[j + 1], s2 = g_esrc[j + 2], s3 = g_esrc[j + 3];
        float2 v0 = *(const float2*)&g_ul[s0 * DOUT + c];
        float2 v1 = *(const float2*)&g_ul[s1 * DOUT + c];
        float2 v2 = *(const float2*)&g_ul[s2 * DOUT + c];
        float2 v3 = *(const float2*)&g_ul[s3 * DOUT + c];
        acc.x += (v0.x + v1.x) + (v2.x + v3.x);
        acc.y += (v0.y + v1.y) + (v2.y + v3.y);
    }
    for (; j < hi; j++) {
        int s = g_esrc[j];
        float2 v = *(const float2*)&g_ul[s * DOUT + c];
        acc.x += v.x; acc.y += v.y;
    }
    float invd = 1.0f / (float)max(hi - lo, 1);
    float2 r  = *(const float2*)&g_ur[gw * DOUT + c];
    float2 bb = *(const float2*)&b2[c];
    float2 o;
    o.x = fmaf(acc.x, invd, r.x + bb.x);
    o.y = fmaf(acc.y, invd, r.y + bb.y);
    *(float2*)&out[gw * DOUT + c] = o;
}

// ---------------- launch ----------------
extern "C" void kernel_launch(void* const* d_in, const int* in_sizes, int n_in,
                              void* d_out, int out_size) {
    const float* x   = (const float*)d_in[0];
    const void*  ei  = d_in[1];                 // int32 OR int64 — detected on device
    const float* Wl1 = (const float*)d_in[2];
    const float* Wr1 = (const float*)d_in[3];
    const float* b1  = (const float*)d_in[4];
    const float* Wl2 = (const float*)d_in[5];
    const float* Wr2 = (const float*)d_in[6];
    const float* b2  = (const float*)d_in[7];
    float* out = (float*)d_out;

    // edge dtype detect + CSR build (shared by both layers)
    detect_kernel<<<1, 256>>>((const int*)ei);
    zero_deg_kernel<<<(NN + 255) / 256, 256>>>();
    hist_kernel<<<(EE + 255) / 256, 256>>>(ei);
    scan_kernel<<<1, 1024>>>();
    fill_kernel<<<(EE + 255) / 256, 256>>>(ei);

    const int gemm_grid = (NN + 127) / 128;  // 391

    // layer 1 projections
    gemm_zl_kernel<<<gemm_grid, 256>>>(x, Wl1);
    gemm_zr_kernel<<<gemm_grid, 256>>>(x, Wr1);
    // fused aggregate + bias + relu
    agg_epi1_kernel<<<(NN * 32 + 255) / 256, 256>>>(b1);

    // layer 2 projections
    gemm_ul_kernel<<<gemm_grid, 256>>>(Wl2);
    gemm_ur_kernel<<<gemm_grid, 256>>>(Wr2);
    // fused aggregate + bias -> output
    agg_epi2_kernel<<<(NN * 32 + 255) / 256, 256>>>(b2, out);
}

// round 5
// speedup vs baseline: 1.3056x; 1.3056x over previous
#include <cuda_runtime.h>

#define NN 50000
#define EE 800000
#define KDIM 128
#define DHID 128
#define DOUT 64
#define NB   ((NN + 255) / 256)   // 196 scan blocks

// ---------------- scratch (device globals; no allocs allowed) ----------------
__device__ int g_is64;             // 1 if edge_index is int64, 0 if int32
__device__ int g_deg[NN];
__device__ int g_rowstart[NN + 1];
__device__ int g_cursor[NN];
__device__ int g_esrc[EE];
__device__ int g_bsum[NB];
__device__ int g_boff[NB + 1];

__device__ float g_zl[NN * DHID];  // x @ W_l1  (gets aggregated)
__device__ float g_zr[NN * DHID];  // x @ W_r1  (self term)
__device__ float g_h [NN * DHID];  // layer-1 output
__device__ float g_ul[NN * DOUT];  // h @ W_l2  (gets aggregated)
__device__ float g_ur[NN * DOUT];  // h @ W_r2  (self term)

// ---------------- edge dtype detection ----------------
// int64 little-endian with values in [0, NN): odd 32-bit words are all 0.
// int32: odd words are random edge endpoints, ~never all zero over 1024 samples.
__global__ void detect_kernel(const int* __restrict__ ei32) {
    __shared__ int nz;
    if (threadIdx.x == 0) nz = 0;
    __syncthreads();
    for (int i = threadIdx.x; i < 1024; i += blockDim.x) {
        if (ei32[2 * i + 1] != 0) nz = 1;   // benign race
    }
    __syncthreads();
    if (threadIdx.x == 0) g_is64 = (nz == 0) ? 1 : 0;
}

__device__ __forceinline__ int load_src(const void* ei, int e) {
    return g_is64 ? (int)((const long long*)ei)[e] : ((const int*)ei)[e];
}
__device__ __forceinline__ int load_dst(const void* ei, int e) {
    return g_is64 ? (int)((const long long*)ei)[EE + e] : ((const int*)ei)[EE + e];
}

// ---------------- CSR build ----------------
__global__ void zero_deg_kernel() {
    int i = blockIdx.x * blockDim.x + threadIdx.x;
    if (i < NN) g_deg[i] = 0;
}

__global__ void hist_kernel(const void* __restrict__ ei) {
    int e = blockIdx.x * blockDim.x + threadIdx.x;
    if (e < EE) {
        int d = load_dst(ei, e);
        if ((unsigned)d < NN) atomicAdd(&g_deg[d], 1);
    }
}

// ---- coalesced 3-phase scan (replaces the 81.5us single-block scan) ----
// A: per-block inclusive scan of 256 degrees; exclusive prefix -> g_rowstart (temp),
//    block total -> g_bsum.
__global__ void scanA_kernel() {
    __shared__ int sh[256];
    const int t = threadIdx.x;
    const int i = blockIdx.x * 256 + t;
    int v = (i < NN) ? g_deg[i] : 0;
    sh[t] = v;
    __syncthreads();
#pragma unroll
    for (int off = 1; off < 256; off <<= 1) {
        int u = (t >= off) ? sh[t - off] : 0;
        __syncthreads();
        sh[t] += u;
        __syncthreads();
    }
    if (i < NN) g_rowstart[i] = sh[t] - v;        // exclusive local prefix
    if (t == 255) g_bsum[blockIdx.x] = sh[255];   // block total
}

// B: scan the NB block sums -> exclusive offsets, plus grand total at g_boff[NB].
__global__ void scanB_kernel() {
    __shared__ int sh[256];
    const int t = threadIdx.x;
    int v = (t < NB) ? g_bsum[t] : 0;
    sh[t] = v;
    __syncthreads();
#pragma unroll
    for (int off = 1; off < 256; off <<= 1) {
        int u = (t >= off) ? sh[t - off] : 0;
        __syncthreads();
        sh[t] += u;
        __syncthreads();
    }
    if (t < NB) g_boff[t] = sh[t] - v;            // exclusive
    if (t == NB - 1) g_boff[NB] = sh[t];          // grand total
}

// C: add block offsets, init cursor, terminator.
__global__ void scanC_kernel() {
    const int i = blockIdx.x * 256 + threadIdx.x;
    if (i < NN) {
        int r = g_rowstart[i] + g_boff[blockIdx.x];
        g_rowstart[i] = r;
        g_cursor[i]   = r;
    }
    if (i == 0) g_rowstart[NN] = g_boff[NB];
}

__global__ void fill_kernel(const void* __restrict__ ei) {
    int e = blockIdx.x * blockDim.x + threadIdx.x;
    if (e < EE) {
        int d = load_dst(ei, e);
        int s = load_src(ei, e);
        if ((unsigned)d < NN && (unsigned)s < NN) {
            int pos = atomicAdd(&g_cursor[d], 1);
            g_esrc[pos] = s;
        }
    }
}

// ---------------- fp32 tiled GEMM body: C[M x BN] = A[M x 128] @ B[128 x BN] ----------------
// BM=128, BK=16, 256 threads, TMxTN register tiles. Scratch buffers are bound
// in DEVICE code by thin wrappers (device-formed addresses are always valid).
template <int BN, int TN>
__device__ __forceinline__
void gemm_body(const float* __restrict__ A, const float* __restrict__ B,
               float* __restrict__ C) {
    const int BM = 128, BK = 16, K = KDIM, TM = 8, M = NN;
    __shared__ float As[BK][BM + 4];
    __shared__ float Bs[BK][BN];

    const int tid = threadIdx.x;
    const int tx = tid % (BN / TN);    // column-threads
    const int ty = tid / (BN / TN);    // row-threads
    const int row0 = blockIdx.x * BM;

    float acc[TM][TN];
#pragma unroll
    for (int i = 0; i < TM; i++)
#pragma unroll
        for (int n = 0; n < TN; n++) acc[i][n] = 0.0f;

    for (int k0 = 0; k0 < K; k0 += BK) {
        // load A tile (BM x BK), store transposed into As[k][m]
#pragma unroll
        for (int p = 0; p < (BM * BK) / (256 * 4); p++) {
            int idx = (p * 256 + tid) * 4;
            int m = idx / BK;
            int kk = idx % BK;       // multiple of 4
            float4 v = make_float4(0.f, 0.f, 0.f, 0.f);
            int row = row0 + m;
            if (row < M) v = *(const float4*)&A[row * K + k0 + kk];
            As[kk + 0][m] = v.x;
            As[kk + 1][m] = v.y;
            As[kk + 2][m] = v.z;
            As[kk + 3][m] = v.w;
        }
        // load B tile (BK x BN)
#pragma unroll
        for (int p = 0; p < (BK * BN) / (256 * 4); p++) {
            int idx = (p * 256 + tid) * 4;
            int kk = idx / BN;
            int j = idx % BN;
            *(float4*)&Bs[kk][j] = *(const float4*)&B[(k0 + kk) * BN + j];
        }
        __syncthreads();

#pragma unroll
        for (int k = 0; k < BK; k++) {
            float a[TM];
            *(float4*)&a[0] = *(const float4*)&As[k][ty * TM];
            *(float4*)&a[4] = *(const float4*)&As[k][ty * TM + 4];
            float b[TN];
            *(float4*)&b[0] = *(const float4*)&Bs[k][tx * TN];
            if constexpr (TN == 8) {
                *(float4*)&b[4] = *(const float4*)&Bs[k][tx * TN + 4];
            }
#pragma unroll
            for (int i = 0; i < TM; i++)
#pragma unroll
                for (int n = 0; n < TN; n++) acc[i][n] = fmaf(a[i], b[n], acc[i][n]);
        }
        __syncthreads();
    }

#pragma unroll
    for (int i = 0; i < TM; i++) {
        int row = row0 + ty * TM + i;
        if (row < M) {
#pragma unroll
            for (int n = 0; n < TN; n += 4) {
                float4 v = make_float4(acc[i][n], acc[i][n + 1], acc[i][n + 2], acc[i][n + 3]);
                *(float4*)&C[row * BN + tx * TN + n] = v;
            }
        }
    }
}

// Wrappers: scratch buffers bound on the DEVICE side only.
__global__ __launch_bounds__(256) void gemm_zl_kernel(const float* __restrict__ x,
                                                      const float* __restrict__ W) {
    gemm_body<128, 8>(x, W, g_zl);
}
__global__ __launch_bounds__(256) void gemm_zr_kernel(const float* __restrict__ x,
                                                      const float* __restrict__ W) {
    gemm_body<128, 8>(x, W, g_zr);
}
__global__ __launch_bounds__(256) void gemm_ul_kernel(const float* __restrict__ W) {
    gemm_body<64, 4>(g_h, W, g_ul);
}
__global__ __launch_bounds__(256) void gemm_ur_kernel(const float* __restrict__ W) {
    gemm_body<64, 4>(g_h, W, g_ur);
}

// ---------------- fused mean-aggregate + epilogue ----------------
// layer 1: h = relu(mean_agg(zl) + zr + b1), D=128, one warp per node, float4/lane
__global__ void agg_epi1_kernel(const float* __restrict__ b1) {
    int gw = (blockIdx.x * blockDim.x + threadIdx.x) >> 5;
    if (gw >= NN) return;
    int lane = threadIdx.x & 31;
    int c = lane * 4;
    int lo = g_rowstart[gw], hi = g_rowstart[gw + 1];

    float4 acc = make_float4(0.f, 0.f, 0.f, 0.f);
    int j = lo;
    for (; j + 4 <= hi; j += 4) {
        int s0 = g_esrc[j], s1 = g_esrc[j + 1], s2 = g_esrc[j + 2], s3 = g_esrc[j + 3];
        float4 v0 = *(const float4*)&g_zl[s0 * DHID + c];
        float4 v1 = *(const float4*)&g_zl[s1 * DHID + c];
        float4 v2 = *(const float4*)&g_zl[s2 * DHID + c];
        float4 v3 = *(const float4*)&g_zl[s3 * DHID + c];
        acc.x += (v0.x + v1.x) + (v2.x + v3.x);
        acc.y += (v0.y + v1.y) + (v2.y + v3.y);
        acc.z += (v0.z + v1.z) + (v2.z + v3.z);
        acc.w += (v0.w + v1.w) + (v2.w + v3.w);
    }
    for (; j < hi; j++) {
        int s = g_esrc[j];
        float4 v = *(const float4*)&g_zl[s * DHID + c];
        acc.x += v.x; acc.y += v.y; acc.z += v.z; acc.w += v.w;
    }
    float invd = 1.0f / (float)max(hi - lo, 1);
    float4 r  = *(const float4*)&g_zr[gw * DHID + c];
    float4 bb = *(const float4*)&b1[c];
    float4 o;
    o.x = fmaxf(fmaf(acc.x, invd, r.x + bb.x), 0.f);
    o.y = fmaxf(fmaf(acc.y, invd, r.y + bb.y), 0.f);
    o.z = fmaxf(fmaf(acc.z, invd, r.z + bb.z), 0.f);
    o.w = fmaxf(fmaf(acc.w, invd, r.w + bb.w), 0.f);
    *(float4*)&g_h[gw * DHID + c] = o;
}

// layer 2: out = mean_agg(ul) + ur + b2, D=64, one warp per node, float2/lane
__global__ void agg_epi2_kernel(const float* __restrict__ b2, float* __restrict__ out) {
    int gw = (blockIdx.x * blockDim.x + threadIdx.x) >> 5;
    if (gw >= NN) return;
    int lane = threadIdx.x & 31;
    int c = lane * 2;
    int lo = g_rowstart[gw], hi = g_rowstart[gw + 1];

    float2 acc = make_float2(0.f, 0.f);
    int j = lo;
    for (; j + 4 <= hi; j += 4) {
        int s0 = g_esrc[j], s1 = g_esrc[j + 1], s2 = g_esrc[j + 2], s3 = g_esrc[j + 3];
        float2 v0 = *(const float2*)&g_ul[s0 * DOUT + c];
        float2 v1 = *(const float2*)&g_ul[s1 * DOUT + c];
        float2 v2 = *(const float2*)&g_ul[s2 * DOUT + c];
        float2 v3 = *(const float2*)&g_ul[s3 * DOUT + c];
        acc.x += (v0.x + v1.x) + (v2.x + v3.x);
        acc.y += (v0.y + v1.y) + (v2.y + v3.y);
    }
    for (; j < hi; j++) {
        int s = g_esrc[j];
        float2 v = *(const float2*)&g_ul[s * DOUT + c];
        acc.x += v.x; acc.y += v.y;
    }
    float invd = 1.0f / (float)max(hi - lo, 1);
    float2 r  = *(const float2*)&g_ur[gw * DOUT + c];
    float2 bb = *(const float2*)&b2[c];
    float2 o;
    o.x = fmaf(acc.x, invd, r.x + bb.x);
    o.y = fmaf(acc.y, invd, r.y + bb.y);
    *(float2*)&out[gw * DOUT + c] = o;
}

// ---------------- launch ----------------
extern "C" void kernel_launch(void* const* d_in, const int* in_sizes, int n_in,
                              void* d_out, int out_size) {
    const float* x   = (const float*)d_in[0];
    const void*  ei  = d_in[1];                 // int32 OR int64 — detected on device
    const float* Wl1 = (const float*)d_in[2];
    const float* Wr1 = (const float*)d_in[3];
    const float* b1  = (const float*)d_in[4];
    const float* Wl2 = (const float*)d_in[5];
    const float* Wr2 = (const float*)d_in[6];
    const float* b2  = (const float*)d_in[7];
    float* out = (float*)d_out;

    // edge dtype detect + CSR build (shared by both layers)
    detect_kernel<<<1, 256>>>((const int*)ei);
    zero_deg_kernel<<<(NN + 255) / 256, 256>>>();
    hist_kernel<<<(EE + 255) / 256, 256>>>(ei);
    scanA_kernel<<<NB, 256>>>();
    scanB_kernel<<<1, 256>>>();
    scanC_kernel<<<NB, 256>>>();
    fill_kernel<<<(EE + 255) / 256, 256>>>(ei);

    const int gemm_grid = (NN + 127) / 128;  // 391

    // layer 1 projections
    gemm_zl_kernel<<<gemm_grid, 256>>>(x, Wl1);
    gemm_zr_kernel<<<gemm_grid, 256>>>(x, Wr1);
    // fused aggregate + bias + relu
    agg_epi1_kernel<<<(NN * 32 + 255) / 256, 256>>>(b1);

    // layer 2 projections
    gemm_ul_kernel<<<gemm_grid, 256>>>(Wl2);
    gemm_ur_kernel<<<gemm_grid, 256>>>(Wr2);
    // fused aggregate + bias -> output
    agg_epi2_kernel<<<(NN * 32 + 255) / 256, 256>>>(b2, out);
}